// round 8
// baseline (speedup 1.0000x reference)
#include <cuda_runtime.h>
#include <cuda_bf16.h>
#include <math.h>

#define NE 2048
#define NP 32768

// ---------------- static device scratch ----------------
__device__ float g_U[NE * 64];
__device__ float g_V[NE * 64];
__device__ float g_R[NP * 16];
__device__ float4 g_off4[NP * 4];     // per-pair 4 rows of -sgn * R_ji^T R_p
__device__ float g_lvals[NP];
__device__ float g_diag[NE * 16];
__device__ float g_Dinv[NE * 16];
__device__ float4 g_Z4[NE * 64];      // (n, f) -> {z0,z1,z2,z3}
__device__ float g_Xcol[NE * 64];

// ---------------- K0: U = ef@W1[:64]+b1 ; V = ef@W1[64:] ----------------
// grid 128, block 256; 16 nodes per block (4 passes) keeps W1 L1-hot
__global__ void k_uv(const float* __restrict__ ef, const float* __restrict__ W1,
                     const float* __restrict__ b1) {
    int nl = threadIdx.x >> 6, f = threadIdx.x & 63;
    __shared__ float efs[4][64];
    float bv = b1[f];
    for (int g = 0; g < 4; g++) {
        int n = blockIdx.x * 16 + g * 4 + nl;
        efs[nl][f] = ef[n * 64 + f];
        __syncthreads();
        float u = bv, v = 0.f;
        #pragma unroll 8
        for (int k = 0; k < 64; k++) {
            float x = efs[nl][k];
            u = fmaf(x, W1[k * 64 + f], u);
            v = fmaf(x, W1[(64 + k) * 64 + f], v);
        }
        g_U[n * 64 + f] = u;
        g_V[n * 64 + f] = v;
        __syncthreads();
    }
}

// ---------------- K1: per-pair MLP tail -> R, plus L1 gather ------------
// grid 1024, block 256: 8192 warps x 4 pairs each
__global__ void k_pair(const float* __restrict__ L1,
                       const float* __restrict__ W2, const float* __restrict__ b2,
                       const float* __restrict__ W3, const float* __restrict__ b3,
                       const int* __restrict__ eidx) {
    __shared__ float W2T[32][68];   // W2T[out][k], padded for LDS.128
    __shared__ float W3T[16][36];   // W3T[out][k]
    __shared__ float b2s[32], b3s[16];
    __shared__ float insh[8][96];
    int tid = threadIdx.x;
    for (int i = tid; i < 64 * 32; i += 256) {
        int k = i >> 5, o = i & 31;
        W2T[o][k] = W2[i];
    }
    for (int i = tid; i < 32 * 16; i += 256) {
        int k = i >> 4, o = i & 15;
        W3T[o][k] = W3[i];
    }
    if (tid < 32) b2s[tid] = b2[tid];
    if (tid < 16) b3s[tid] = b3[tid];
    __syncthreads();
    int w = tid >> 5, lane = tid & 31;
    int gw = blockIdx.x * 8 + w;
    int o = 2 * lane;
    #pragma unroll
    for (int pi = 0; pi < 4; pi++) {
        int p = gw * 4 + pi;
        int ii = eidx[2 * p], jj = eidx[2 * p + 1];
        if (lane == 0) g_lvals[p] = L1[(size_t)ii * NE + jj];
        float2 uu = *(const float2*)&g_U[ii * 64 + o];
        float2 vv = *(const float2*)&g_V[jj * 64 + o];
        float2 hv;
        hv.x = fmaxf(uu.x + vv.x, 0.f);
        hv.y = fmaxf(uu.y + vv.y, 0.f);
        *(float2*)&insh[w][o] = hv;
        __syncwarp();
        // layer 2: 64 -> 32
        float c = b2s[lane];
        #pragma unroll
        for (int k = 0; k < 64; k += 4) {
            float4 hh = *(const float4*)&insh[w][k];
            float4 ww = *(const float4*)&W2T[lane][k];
            c = fmaf(hh.x, ww.x, c);
            c = fmaf(hh.y, ww.y, c);
            c = fmaf(hh.z, ww.z, c);
            c = fmaf(hh.w, ww.w, c);
        }
        c = fmaxf(c, 0.f);
        insh[w][64 + lane] = c;
        __syncwarp();
        // layer 3: 32 -> 16 (no relu)
        if (lane < 16) {
            float r = b3s[lane];
            #pragma unroll
            for (int k = 0; k < 32; k += 4) {
                float4 hh = *(const float4*)&insh[w][64 + k];
                float4 ww = *(const float4*)&W3T[lane][k];
                r = fmaf(hh.x, ww.x, r);
                r = fmaf(hh.y, ww.y, r);
                r = fmaf(hh.z, ww.z, r);
                r = fmaf(hh.w, ww.w, r);
            }
            g_R[p * 16 + lane] = r;
        }
        __syncwarp();
    }
}

// ---------------- K2: diag + Jacobi Dinv + off blocks + Xt/Z/Xcol -------
// block = 256 threads, 8 nodes (=128 pairs) per block, grid 256
__global__ void k_mid(const float* __restrict__ X, const float* __restrict__ Ws1,
                      const float* __restrict__ Ws2, const int* __restrict__ jiidx) {
    __shared__ float sDb[8][16];
    __shared__ float sDinv[8][16];
    __shared__ float Ysh[8][4][64];
    int tid = threadIdx.x;
    int w = tid >> 5, lane = tid & 31;
    int node = blockIdx.x * 8 + w;

    float Fm[16];
    #pragma unroll
    for (int x = 0; x < 16; x++) Fm[x] = 0.f;
    if (lane < 16) {
        int p = node * 16 + lane;
        float4 r0 = *(const float4*)&g_R[p * 16];
        float4 r1 = *(const float4*)&g_R[p * 16 + 4];
        float4 r2 = *(const float4*)&g_R[p * 16 + 8];
        float4 r3 = *(const float4*)&g_R[p * 16 + 12];
        float Rv[16] = {r0.x, r0.y, r0.z, r0.w, r1.x, r1.y, r1.z, r1.w,
                        r2.x, r2.y, r2.z, r2.w, r3.x, r3.y, r3.z, r3.w};
        #pragma unroll
        for (int a = 0; a < 4; a++)
            #pragma unroll
            for (int b = 0; b < 4; b++) {
                float s = 0.f;
                #pragma unroll
                for (int c = 0; c < 4; c++) s = fmaf(Rv[c * 4 + a], Rv[c * 4 + b], s);
                Fm[a * 4 + b] = s;
            }
    }
    #pragma unroll
    for (int x = 0; x < 16; x++) {
        Fm[x] += __shfl_down_sync(0xffffffffu, Fm[x], 8);
        Fm[x] += __shfl_down_sync(0xffffffffu, Fm[x], 4);
        Fm[x] += __shfl_down_sync(0xffffffffu, Fm[x], 2);
        Fm[x] += __shfl_down_sync(0xffffffffu, Fm[x], 1);
    }
    if (lane == 0) {
        #pragma unroll
        for (int x = 0; x < 16; x++) { sDb[w][x] = Fm[x]; g_diag[node * 16 + x] = Fm[x]; }
    }
    __syncthreads();

    if (tid < 128) {
        int p = blockIdx.x * 128 + tid;
        int jp = jiidx[p];
        float l = g_lvals[p];
        float msg = (l > 0.f) ? -1.f : ((l < 0.f) ? 1.f : 0.f);
        float4 a0 = *(const float4*)&g_R[jp * 16];
        float4 a1 = *(const float4*)&g_R[jp * 16 + 4];
        float4 a2 = *(const float4*)&g_R[jp * 16 + 8];
        float4 a3 = *(const float4*)&g_R[jp * 16 + 12];
        float4 b0 = *(const float4*)&g_R[p * 16];
        float4 b1v = *(const float4*)&g_R[p * 16 + 4];
        float4 b2v = *(const float4*)&g_R[p * 16 + 8];
        float4 b3v = *(const float4*)&g_R[p * 16 + 12];
        float Ra[16] = {a0.x, a0.y, a0.z, a0.w, a1.x, a1.y, a1.z, a1.w,
                        a2.x, a2.y, a2.z, a2.w, a3.x, a3.y, a3.z, a3.w};
        float Rb[16] = {b0.x, b0.y, b0.z, b0.w, b1v.x, b1v.y, b1v.z, b1v.w,
                        b2v.x, b2v.y, b2v.z, b2v.w, b3v.x, b3v.y, b3v.z, b3v.w};
        #pragma unroll
        for (int a = 0; a < 4; a++) {
            float4 row;
            float* rp = (float*)&row;
            #pragma unroll
            for (int b = 0; b < 4; b++) {
                float m = 0.f;
                #pragma unroll
                for (int c = 0; c < 4; c++) m = fmaf(Ra[c * 4 + a], Rb[c * 4 + b], m);
                rp[b] = msg * m;
            }
            g_off4[p * 4 + a] = row;
        }
    } else if (tid < 136) {
        int nl = tid - 128;
        const float eps = 1e-4f;
        float A[4][4], V[4][4];
        #pragma unroll
        for (int a = 0; a < 4; a++)
            #pragma unroll
            for (int b = 0; b < 4; b++) {
                A[a][b] = 0.5f * (sDb[nl][a * 4 + b] + sDb[nl][b * 4 + a]);
                V[a][b] = (a == b) ? 1.f : 0.f;
            }
        #pragma unroll
        for (int a = 0; a < 4; a++) A[a][a] += eps;
        const int PI[6] = {0, 0, 0, 1, 1, 2};
        const int QI[6] = {1, 2, 3, 2, 3, 3};
        #pragma unroll
        for (int sweep = 0; sweep < 6; sweep++) {
            #pragma unroll
            for (int r = 0; r < 6; r++) {
                int p = PI[r], q = QI[r];
                float apq = A[p][q];
                if (fabsf(apq) > 1e-20f) {
                    float theta = (A[q][q] - A[p][p]) / (2.f * apq);
                    float t = copysignf(1.f, theta) / (fabsf(theta) + sqrtf(theta * theta + 1.f));
                    float cth = rsqrtf(t * t + 1.f);
                    float sth = t * cth;
                    float app = A[p][p], aqq = A[q][q];
                    A[p][p] = app - t * apq;
                    A[q][q] = aqq + t * apq;
                    A[p][q] = 0.f; A[q][p] = 0.f;
                    #pragma unroll
                    for (int k = 0; k < 4; k++) {
                        if (k != p && k != q) {
                            float akp = A[k][p], akq = A[k][q];
                            A[k][p] = cth * akp - sth * akq; A[p][k] = A[k][p];
                            A[k][q] = sth * akp + cth * akq; A[q][k] = A[k][q];
                        }
                    }
                    #pragma unroll
                    for (int k = 0; k < 4; k++) {
                        float vkp = V[k][p], vkq = V[k][q];
                        V[k][p] = cth * vkp - sth * vkq;
                        V[k][q] = sth * vkp + cth * vkq;
                    }
                }
            }
        }
        float invs[4];
        #pragma unroll
        for (int k = 0; k < 4; k++) invs[k] = rsqrtf(fmaxf(A[k][k], eps));
        int gnode = blockIdx.x * 8 + nl;
        #pragma unroll
        for (int a = 0; a < 4; a++)
            #pragma unroll
            for (int b = 0; b < 4; b++) {
                float s = 0.f;
                #pragma unroll
                for (int k = 0; k < 4; k++) s = fmaf(V[a][k] * invs[k], V[b][k], s);
                sDinv[nl][a * 4 + b] = s;
                g_Dinv[gnode * 16 + a * 4 + b] = s;
            }
    }
    __syncthreads();

    #pragma unroll
    for (int it = 0; it < 2; it++) {
        int idx = tid + it * 256;
        int nl = idx >> 6, f = idx & 63;
        int n = blockIdx.x * 8 + nl;
        float xr[4];
        #pragma unroll
        for (int b = 0; b < 4; b++) xr[b] = X[(4 * n + b) * 64 + f];
        g_Xcol[n * 64 + f] = 0.25f * (xr[0] + xr[1] + xr[2] + xr[3]);
        #pragma unroll
        for (int a = 0; a < 4; a++) {
            float y = 0.f;
            #pragma unroll
            for (int b = 0; b < 4; b++) y = fmaf(Ws1[a * 4 + b], xr[b], y);
            Ysh[nl][a][f] = y;
        }
    }
    __syncthreads();
    #pragma unroll
    for (int it = 0; it < 2; it++) {
        int idx = tid + it * 256;
        int nl = idx >> 6, f = idx & 63;
        int n = blockIdx.x * 8 + nl;
        float xt[4] = {0.f, 0.f, 0.f, 0.f};
        #pragma unroll 4
        for (int g = 0; g < 64; g++) {
            float w2 = Ws2[g * 64 + f];
            #pragma unroll
            for (int a = 0; a < 4; a++) xt[a] = fmaf(Ysh[nl][a][g], w2, xt[a]);
        }
        float dv[16];
        #pragma unroll
        for (int x = 0; x < 16; x++) dv[x] = sDinv[nl][x];
        float4 z;
        z.x = fmaf(dv[0], xt[0], fmaf(dv[1], xt[1], fmaf(dv[2], xt[2], dv[3] * xt[3])));
        z.y = fmaf(dv[4], xt[0], fmaf(dv[5], xt[1], fmaf(dv[6], xt[2], dv[7] * xt[3])));
        z.z = fmaf(dv[8], xt[0], fmaf(dv[9], xt[1], fmaf(dv[10], xt[2], dv[11] * xt[3])));
        z.w = fmaf(dv[12], xt[0], fmaf(dv[13], xt[1], fmaf(dv[14], xt[2], dv[15] * xt[3])));
        g_Z4[n * 64 + f] = z;
    }
}

// ---------------- K3: hodge + sheaf + residual + output -----------------
// grid 1024, block 512, 2 nodes/block. Thread (nl, f, a): a = low 2 lane bits,
// owns sheaf/residual row a. Cross-row reductions via __shfl over the 4-lane
// group (no shared round-trips, no redundant LDG). Banded 18-row Z/Xcol window
// staged in shared.
__global__ void k_out(const int* __restrict__ eidx, const float* __restrict__ Wh,
                      const float* __restrict__ X, const float* __restrict__ resW,
                      const float* __restrict__ resb, const float* __restrict__ alpha,
                      const float* __restrict__ beta, float* __restrict__ out) {
    int tid = threadIdx.x;
    int nl = tid >> 8;           // 0..1
    int r = tid & 255;
    int f = r >> 2;              // 0..63
    int a = r & 3;               // 0..3 (== lane & 3)
    int lane = tid & 31;
    int i0 = blockIdx.x * 2;
    int i = i0 + nl;

    __shared__ float4 Z4sh[18][64];     // rows i0-8 .. i0+9 (mod NE)
    __shared__ float Xcolsh[18][64];
    __shared__ float4 offs4[2][64];     // 16 neighbors x 4 rows per node
    __shared__ float Xsh[2][4][64];
    __shared__ float hp[2][64];
    __shared__ int jrel[2][16];
    __shared__ float lvsh[2][16];

    // stage banded window: 18*64 = 1152 entries, 512 threads, 3 passes
    #pragma unroll
    for (int t = 0; t < 3; t++) {
        int idx = tid + t * 512;
        if (idx < 1152) {
            int row = idx >> 6, ff = idx & 63;
            int src = (i0 - 8 + row) & (NE - 1);
            Z4sh[row][ff] = g_Z4[src * 64 + ff];
            Xcolsh[row][ff] = g_Xcol[src * 64 + ff];
        }
    }
    // stage X rows (one element per thread), off blocks, neighbor meta
    Xsh[nl][a][f] = X[(4 * i + a) * 64 + f];
    if (r < 64) offs4[nl][r] = g_off4[i * 64 + r];
    if (r < 16) {
        int pp = 16 * i + r;
        int j = eidx[2 * pp + 1];
        jrel[nl][r] = (j - i0 + 8) & (NE - 1);   // in [0, 18)
        lvsh[nl][r] = fabsf(g_lvals[pp]);
    }
    __syncthreads();

    // ---- sheaf row a for (i, f): diag[a,:] zi + sum_k off_k[a,:] zj ----
    float4 zi = Z4sh[8 + nl][f];
    float4 dg = *(const float4*)&g_diag[i * 16 + 4 * a];
    float acc = fmaf(dg.x, zi.x, fmaf(dg.y, zi.y, fmaf(dg.z, zi.z, dg.w * zi.w)));
    #pragma unroll
    for (int k = 0; k < 16; k++) {
        float4 zj = Z4sh[jrel[nl][k]][f];
        float4 o = offs4[nl][k * 4 + a];
        acc = fmaf(o.x, zj.x, fmaf(o.y, zj.y, fmaf(o.z, zj.z, fmaf(o.w, zj.w, acc))));
    }
    // gather all 4 row-accumulators from the 4-lane group, apply Dinv row a
    int base = lane & ~3;
    float ac0 = __shfl_sync(0xffffffffu, acc, base + 0);
    float ac1 = __shfl_sync(0xffffffffu, acc, base + 1);
    float ac2 = __shfl_sync(0xffffffffu, acc, base + 2);
    float ac3 = __shfl_sync(0xffffffffu, acc, base + 3);
    float4 dv = *(const float4*)&g_Dinv[i * 16 + 4 * a];
    float sh = fmaf(dv.x, ac0, fmaf(dv.y, ac1, fmaf(dv.z, ac2, dv.w * ac3)));

    // ---- hodge partial: a-group covers neighbors 4a..4a+3 ----
    float s = 0.f;
    #pragma unroll
    for (int p = 0; p < 16; p++) s += lvsh[nl][p];
    float inv = 1.f / (s + 1e-8f);
    float hacc = (a == 0) ? Xcolsh[8 + nl][f] : 0.f;
    #pragma unroll
    for (int p = 0; p < 4; p++) {
        int pp = 4 * a + p;
        hacc = fmaf(lvsh[nl][pp] * inv, Xcolsh[jrel[nl][pp]][f], hacc);
    }
    float hrow = __shfl_sync(0xffffffffu, hacc, base + 0)
               + __shfl_sync(0xffffffffu, hacc, base + 1)
               + __shfl_sync(0xffffffffu, hacc, base + 2)
               + __shfl_sync(0xffffffffu, hacc, base + 3);
    if (a == 0) hp[nl][f] = hrow;

    // ---- residual row a ----
    float rv = resb[f];
    #pragma unroll 8
    for (int k = 0; k < 64; k++)
        rv = fmaf(Xsh[nl][a][k], resW[k * 64 + f], rv);
    __syncthreads();

    // ---- hodge matmul (4-lane redundant; Wh reads broadcast) ----
    float h = 0.f;
    #pragma unroll 8
    for (int g = 0; g < 64; g++)
        h = fmaf(hp[nl][g], Wh[g * 64 + f], h);

    float sa = 1.f / (1.f + expf(-alpha[0]));
    float sb = 1.f / (1.f + expf(-beta[0]));
    float e = (sh > 0.f) ? sh : expm1f(sh);
    out[(4 * i + a) * 64 + f] = rv - sa * h - sb * e;
}

extern "C" void kernel_launch(void* const* d_in, const int* in_sizes, int n_in,
                              void* d_out, int out_size) {
    const float* ef    = (const float*)d_in[0];
    const float* L1    = (const float*)d_in[1];
    const float* X     = (const float*)d_in[2];
    const float* W1    = (const float*)d_in[3];
    const float* b1    = (const float*)d_in[4];
    const float* W2    = (const float*)d_in[5];
    const float* b2    = (const float*)d_in[6];
    const float* W3    = (const float*)d_in[7];
    const float* b3    = (const float*)d_in[8];
    const float* Wh    = (const float*)d_in[9];
    const float* Ws1   = (const float*)d_in[10];
    const float* Ws2   = (const float*)d_in[11];
    const float* resW  = (const float*)d_in[12];
    const float* resb  = (const float*)d_in[13];
    const float* alpha = (const float*)d_in[14];
    const float* beta  = (const float*)d_in[15];
    const int*   eidx  = (const int*)d_in[16];
    const int*   jiidx = (const int*)d_in[17];
    float* out = (float*)d_out;

    k_uv<<<128, 256>>>(ef, W1, b1);
    k_pair<<<1024, 256>>>(L1, W2, b2, W3, b3, eidx);
    k_mid<<<256, 256>>>(X, Ws1, Ws2, jiidx);
    k_out<<<1024, 512>>>(eidx, Wh, X, resW, resb, alpha, beta, out);
}

// round 10
// speedup vs baseline: 1.4820x; 1.4820x over previous
#include <cuda_runtime.h>
#include <cuda_bf16.h>
#include <math.h>

#define NE 2048
#define NP 32768

// ---------------- static device scratch ----------------
__device__ float g_U[NE * 64];
__device__ float g_V[NE * 64];
__device__ float g_R[NP * 16];
__device__ float4 g_off4[NP * 4];     // per-pair 4 rows of -sgn * R_ji^T R_p
__device__ float g_lvals[NP];
__device__ float g_diag[NE * 16];
__device__ float g_Dinv[NE * 16];
__device__ float4 g_Z4[NE * 64];      // (n, f) -> {z0,z1,z2,z3}
__device__ float4 g_Xt4[NE * 64];     // (n, f) -> X_t rows
__device__ float4 g_P4[NE * 64];      // partial: X@resW+resb - sa*hodge
__device__ float g_Xcol[NE * 64];

// ---------------- K0: U, V, Xcol, Xt ------------------------------------
// grid 512, block 256, 4 nodes/block
__global__ void k_pre(const float* __restrict__ ef, const float* __restrict__ W1,
                      const float* __restrict__ b1, const float* __restrict__ X,
                      const float* __restrict__ Ws1, const float* __restrict__ Ws2) {
    int nl = threadIdx.x >> 6, f = threadIdx.x & 63;
    int n = blockIdx.x * 4 + nl;
    __shared__ float efs[4][64];
    __shared__ float Ysh[4][4][64];
    efs[nl][f] = ef[n * 64 + f];
    float xr[4];
    #pragma unroll
    for (int b = 0; b < 4; b++) xr[b] = X[(4 * n + b) * 64 + f];
    g_Xcol[n * 64 + f] = 0.25f * (xr[0] + xr[1] + xr[2] + xr[3]);
    #pragma unroll
    for (int a = 0; a < 4; a++) {
        float y = 0.f;
        #pragma unroll
        for (int b = 0; b < 4; b++) y = fmaf(Ws1[a * 4 + b], xr[b], y);
        Ysh[nl][a][f] = y;
    }
    __syncthreads();
    float u = b1[f], v = 0.f;
    #pragma unroll 8
    for (int k = 0; k < 64; k++) {
        float x = efs[nl][k];
        u = fmaf(x, W1[k * 64 + f], u);
        v = fmaf(x, W1[(64 + k) * 64 + f], v);
    }
    g_U[n * 64 + f] = u;
    g_V[n * 64 + f] = v;
    float xt[4] = {0.f, 0.f, 0.f, 0.f};
    #pragma unroll 4
    for (int g = 0; g < 64; g++) {
        float w2 = Ws2[g * 64 + f];
        #pragma unroll
        for (int a = 0; a < 4; a++) xt[a] = fmaf(Ysh[nl][a][g], w2, xt[a]);
    }
    float4 o;
    o.x = xt[0]; o.y = xt[1]; o.z = xt[2]; o.w = xt[3];
    g_Xt4[n * 64 + f] = o;
}

// ---------------- K1: per-pair MLP tail -> R, plus L1 gather ------------
// grid 512, block 256: 8 warps x 8 pairs each (R7 config)
__global__ void k_pair(const float* __restrict__ L1,
                       const float* __restrict__ W2, const float* __restrict__ b2,
                       const float* __restrict__ W3, const float* __restrict__ b3,
                       const int* __restrict__ eidx) {
    __shared__ float W2T[32][68];
    __shared__ float W3T[16][36];
    __shared__ float b2s[32], b3s[16];
    __shared__ float insh[8][96];
    int tid = threadIdx.x;
    for (int i = tid; i < 64 * 32; i += 256) {
        int k = i >> 5, o = i & 31;
        W2T[o][k] = W2[i];
    }
    for (int i = tid; i < 32 * 16; i += 256) {
        int k = i >> 4, o = i & 15;
        W3T[o][k] = W3[i];
    }
    if (tid < 32) b2s[tid] = b2[tid];
    if (tid < 16) b3s[tid] = b3[tid];
    __syncthreads();
    int w = tid >> 5, lane = tid & 31;
    int gw = blockIdx.x * 8 + w;
    int o = 2 * lane;
    #pragma unroll
    for (int pi = 0; pi < 8; pi++) {
        int p = gw * 8 + pi;
        int ii = eidx[2 * p], jj = eidx[2 * p + 1];
        if (lane == 0) g_lvals[p] = L1[(size_t)ii * NE + jj];
        float2 uu = *(const float2*)&g_U[ii * 64 + o];
        float2 vv = *(const float2*)&g_V[jj * 64 + o];
        float2 hv;
        hv.x = fmaxf(uu.x + vv.x, 0.f);
        hv.y = fmaxf(uu.y + vv.y, 0.f);
        *(float2*)&insh[w][o] = hv;
        __syncwarp();
        float c = b2s[lane];
        #pragma unroll
        for (int k = 0; k < 64; k += 4) {
            float4 hh = *(const float4*)&insh[w][k];
            float4 ww = *(const float4*)&W2T[lane][k];
            c = fmaf(hh.x, ww.x, c);
            c = fmaf(hh.y, ww.y, c);
            c = fmaf(hh.z, ww.z, c);
            c = fmaf(hh.w, ww.w, c);
        }
        c = fmaxf(c, 0.f);
        insh[w][64 + lane] = c;
        __syncwarp();
        if (lane < 16) {
            float r = b3s[lane];
            #pragma unroll
            for (int k = 0; k < 32; k += 4) {
                float4 hh = *(const float4*)&insh[w][64 + k];
                float4 ww = *(const float4*)&W3T[lane][k];
                r = fmaf(hh.x, ww.x, r);
                r = fmaf(hh.y, ww.y, r);
                r = fmaf(hh.z, ww.z, r);
                r = fmaf(hh.w, ww.w, r);
            }
            g_R[p * 16 + lane] = r;
        }
        __syncwarp();
    }
}

// ---------------- K2: diag/Jacobi/off + Z + hodge + residual partial ----
// grid 512, block 256, 4 nodes (=64 pairs) per block
__global__ void k_mid(const int* __restrict__ eidx, const int* __restrict__ jiidx,
                      const float* __restrict__ Wh, const float* __restrict__ X,
                      const float* __restrict__ resW, const float* __restrict__ resb,
                      const float* __restrict__ alpha) {
    __shared__ float sDb[4][16];
    __shared__ float sDinv[4][16];
    __shared__ float Xcw[20][64];
    __shared__ float Xsh[4][4][64];
    __shared__ float hps[4][64];
    __shared__ int jrel[4][16];
    __shared__ float lv[4][16];
    int tid = threadIdx.x;
    int w = tid >> 5, lane = tid & 31;
    int i0 = blockIdx.x * 4;

    // phase A: diag for nodes i0..i0+3 (warps 0-3)
    if (w < 4) {
        int node = i0 + w;
        float Fm[16];
        #pragma unroll
        for (int x = 0; x < 16; x++) Fm[x] = 0.f;
        if (lane < 16) {
            int p = node * 16 + lane;
            float4 r0 = *(const float4*)&g_R[p * 16];
            float4 r1 = *(const float4*)&g_R[p * 16 + 4];
            float4 r2 = *(const float4*)&g_R[p * 16 + 8];
            float4 r3 = *(const float4*)&g_R[p * 16 + 12];
            float Rv[16] = {r0.x, r0.y, r0.z, r0.w, r1.x, r1.y, r1.z, r1.w,
                            r2.x, r2.y, r2.z, r2.w, r3.x, r3.y, r3.z, r3.w};
            #pragma unroll
            for (int a = 0; a < 4; a++)
                #pragma unroll
                for (int b = 0; b < 4; b++) {
                    float s = 0.f;
                    #pragma unroll
                    for (int c = 0; c < 4; c++) s = fmaf(Rv[c * 4 + a], Rv[c * 4 + b], s);
                    Fm[a * 4 + b] = s;
                }
        }
        #pragma unroll
        for (int x = 0; x < 16; x++) {
            Fm[x] += __shfl_down_sync(0xffffffffu, Fm[x], 8);
            Fm[x] += __shfl_down_sync(0xffffffffu, Fm[x], 4);
            Fm[x] += __shfl_down_sync(0xffffffffu, Fm[x], 2);
            Fm[x] += __shfl_down_sync(0xffffffffu, Fm[x], 1);
        }
        if (lane == 0) {
            #pragma unroll
            for (int x = 0; x < 16; x++) { sDb[w][x] = Fm[x]; g_diag[node * 16 + x] = Fm[x]; }
        }
    }
    __syncthreads();

    // phase B: off blocks (tid<64) + Jacobi (tid 64..67)
    if (tid < 64) {
        int p = i0 * 16 + tid;
        int jp = jiidx[p];
        float l = g_lvals[p];
        float msg = (l > 0.f) ? -1.f : ((l < 0.f) ? 1.f : 0.f);
        float4 a0 = *(const float4*)&g_R[jp * 16];
        float4 a1 = *(const float4*)&g_R[jp * 16 + 4];
        float4 a2 = *(const float4*)&g_R[jp * 16 + 8];
        float4 a3 = *(const float4*)&g_R[jp * 16 + 12];
        float4 b0 = *(const float4*)&g_R[p * 16];
        float4 b1v = *(const float4*)&g_R[p * 16 + 4];
        float4 b2v = *(const float4*)&g_R[p * 16 + 8];
        float4 b3v = *(const float4*)&g_R[p * 16 + 12];
        float Ra[16] = {a0.x, a0.y, a0.z, a0.w, a1.x, a1.y, a1.z, a1.w,
                        a2.x, a2.y, a2.z, a2.w, a3.x, a3.y, a3.z, a3.w};
        float Rb[16] = {b0.x, b0.y, b0.z, b0.w, b1v.x, b1v.y, b1v.z, b1v.w,
                        b2v.x, b2v.y, b2v.z, b2v.w, b3v.x, b3v.y, b3v.z, b3v.w};
        #pragma unroll
        for (int a = 0; a < 4; a++) {
            float4 row;
            float* rp = (float*)&row;
            #pragma unroll
            for (int b = 0; b < 4; b++) {
                float m = 0.f;
                #pragma unroll
                for (int c = 0; c < 4; c++) m = fmaf(Ra[c * 4 + a], Rb[c * 4 + b], m);
                rp[b] = msg * m;
            }
            g_off4[p * 4 + a] = row;
        }
    } else if (tid < 68) {
        int nl = tid - 64;
        const float eps = 1e-4f;
        float A[4][4], V[4][4];
        #pragma unroll
        for (int a = 0; a < 4; a++)
            #pragma unroll
            for (int b = 0; b < 4; b++) {
                A[a][b] = 0.5f * (sDb[nl][a * 4 + b] + sDb[nl][b * 4 + a]);
                V[a][b] = (a == b) ? 1.f : 0.f;
            }
        #pragma unroll
        for (int a = 0; a < 4; a++) A[a][a] += eps;
        const int PI[6] = {0, 0, 0, 1, 1, 2};
        const int QI[6] = {1, 2, 3, 2, 3, 3};
        #pragma unroll
        for (int sweep = 0; sweep < 6; sweep++) {
            #pragma unroll
            for (int r = 0; r < 6; r++) {
                int p = PI[r], q = QI[r];
                float apq = A[p][q];
                if (fabsf(apq) > 1e-20f) {
                    float theta = (A[q][q] - A[p][p]) / (2.f * apq);
                    float t = copysignf(1.f, theta) / (fabsf(theta) + sqrtf(theta * theta + 1.f));
                    float cth = rsqrtf(t * t + 1.f);
                    float sth = t * cth;
                    float app = A[p][p], aqq = A[q][q];
                    A[p][p] = app - t * apq;
                    A[q][q] = aqq + t * apq;
                    A[p][q] = 0.f; A[q][p] = 0.f;
                    #pragma unroll
                    for (int k = 0; k < 4; k++) {
                        if (k != p && k != q) {
                            float akp = A[k][p], akq = A[k][q];
                            A[k][p] = cth * akp - sth * akq; A[p][k] = A[k][p];
                            A[k][q] = sth * akp + cth * akq; A[q][k] = A[k][q];
                        }
                    }
                    #pragma unroll
                    for (int k = 0; k < 4; k++) {
                        float vkp = V[k][p], vkq = V[k][q];
                        V[k][p] = cth * vkp - sth * vkq;
                        V[k][q] = sth * vkp + cth * vkq;
                    }
                }
            }
        }
        float invs[4];
        #pragma unroll
        for (int k = 0; k < 4; k++) invs[k] = rsqrtf(fmaxf(A[k][k], eps));
        int gnode = i0 + nl;
        #pragma unroll
        for (int a = 0; a < 4; a++)
            #pragma unroll
            for (int b = 0; b < 4; b++) {
                float s = 0.f;
                #pragma unroll
                for (int k = 0; k < 4; k++) s = fmaf(V[a][k] * invs[k], V[b][k], s);
                sDinv[nl][a * 4 + b] = s;
                g_Dinv[gnode * 16 + a * 4 + b] = s;
            }
    }

    // phase D staging (independent of B results): Xcol window, X rows, meta
    #pragma unroll
    for (int t = 0; t < 5; t++) {
        int idx = tid + t * 256;          // 0..1279
        int row = idx >> 6, ff = idx & 63;
        int src = (i0 - 8 + row) & (NE - 1);
        Xcw[row][ff] = g_Xcol[src * 64 + ff];
    }
    #pragma unroll
    for (int t = 0; t < 4; t++) {
        int idx = tid + t * 256;          // 0..1023
        int nn = idx >> 8, rest = idx & 255;
        int b = rest >> 6, ff = rest & 63;
        Xsh[nn][b][ff] = X[(4 * (i0 + nn) + b) * 64 + ff];
    }
    if (tid < 64) {
        int nn = tid >> 4, k = tid & 15;
        int pp = (i0 + nn) * 16 + k;
        int j = eidx[2 * pp + 1];
        jrel[nn][k] = (j - i0 + 8) & (NE - 1);   // in [0, 20)
        lv[nn][k] = fabsf(g_lvals[pp]);
    }
    __syncthreads();

    int nl = tid >> 6, f = tid & 63;
    int n = i0 + nl;

    // phase C: Z = Dinv @ Xt
    {
        float4 xt = g_Xt4[n * 64 + f];
        float dv[16];
        #pragma unroll
        for (int x = 0; x < 16; x++) dv[x] = sDinv[nl][x];
        float4 z;
        z.x = fmaf(dv[0], xt.x, fmaf(dv[1], xt.y, fmaf(dv[2], xt.z, dv[3] * xt.w)));
        z.y = fmaf(dv[4], xt.x, fmaf(dv[5], xt.y, fmaf(dv[6], xt.z, dv[7] * xt.w)));
        z.z = fmaf(dv[8], xt.x, fmaf(dv[9], xt.y, fmaf(dv[10], xt.z, dv[11] * xt.w)));
        z.w = fmaf(dv[12], xt.x, fmaf(dv[13], xt.y, fmaf(dv[14], xt.z, dv[15] * xt.w)));
        g_Z4[n * 64 + f] = z;
    }

    // phase D: hodge + residual partial
    float s = 0.f;
    #pragma unroll
    for (int p = 0; p < 16; p++) s += lv[nl][p];
    float inv = 1.f / (s + 1e-8f);
    float hp = Xcw[8 + nl][f];
    #pragma unroll
    for (int p = 0; p < 16; p++)
        hp = fmaf(lv[nl][p] * inv, Xcw[jrel[nl][p]][f], hp);
    hps[nl][f] = hp;
    __syncthreads();
    float h = 0.f;
    #pragma unroll 4
    for (int g = 0; g < 64; g++) h = fmaf(hps[nl][g], Wh[g * 64 + f], h);
    float sa = 1.f / (1.f + expf(-alpha[0]));
    float bb = resb[f];
    float r[4];
    #pragma unroll
    for (int b = 0; b < 4; b++) r[b] = bb;
    #pragma unroll 4
    for (int k = 0; k < 64; k++) {
        float wv = resW[k * 64 + f];
        #pragma unroll
        for (int b = 0; b < 4; b++) r[b] = fmaf(Xsh[nl][b][k], wv, r[b]);
    }
    float4 pr;
    pr.x = r[0] - sa * h; pr.y = r[1] - sa * h;
    pr.z = r[2] - sa * h; pr.w = r[3] - sa * h;
    g_P4[n * 64 + f] = pr;
}

// ---------------- K3: sheaf + combine -----------------------------------
// grid 512, block 256, 4 nodes/block (R7 sheaf structure)
__global__ void k_out(const int* __restrict__ eidx, const float* __restrict__ beta,
                      float* __restrict__ out) {
    int tid = threadIdx.x;
    int nl = tid >> 6, f = tid & 63;
    int i0 = blockIdx.x * 4;
    int i = i0 + nl;
    __shared__ float4 Z4sh[20][64];
    __shared__ float4 offs4[4][64];
    __shared__ int jrel[4][16];

    #pragma unroll
    for (int t = 0; t < 5; t++) {
        int idx = tid + t * 256;
        int row = idx >> 6, ff = idx & 63;
        int src = (i0 - 8 + row) & (NE - 1);
        Z4sh[row][ff] = g_Z4[src * 64 + ff];
    }
    offs4[nl][f] = g_off4[i * 64 + f];
    if (f < 16) {
        int pp = 16 * i + f;
        int j = eidx[2 * pp + 1];
        jrel[nl][f] = (j - i0 + 8) & (NE - 1);
    }
    __syncthreads();

    float4 zi = Z4sh[8 + nl][f];
    const float4* dgr = (const float4*)&g_diag[i * 16];
    float accs[4];
    #pragma unroll
    for (int a = 0; a < 4; a++) {
        float4 d = dgr[a];
        accs[a] = fmaf(d.x, zi.x, fmaf(d.y, zi.y, fmaf(d.z, zi.z, d.w * zi.w)));
    }
    #pragma unroll
    for (int k = 0; k < 16; k++) {
        float4 zj = Z4sh[jrel[nl][k]][f];
        #pragma unroll
        for (int a = 0; a < 4; a++) {
            float4 o = offs4[nl][k * 4 + a];
            accs[a] = fmaf(o.x, zj.x, fmaf(o.y, zj.y, fmaf(o.z, zj.z, fmaf(o.w, zj.w, accs[a]))));
        }
    }
    const float4* dvr = (const float4*)&g_Dinv[i * 16];
    float sh[4];
    #pragma unroll
    for (int a = 0; a < 4; a++) {
        float4 d = dvr[a];
        sh[a] = fmaf(d.x, accs[0], fmaf(d.y, accs[1], fmaf(d.z, accs[2], d.w * accs[3])));
    }

    float4 pr = g_P4[i * 64 + f];
    float sb = 1.f / (1.f + expf(-beta[0]));
    float prr[4] = {pr.x, pr.y, pr.z, pr.w};
    #pragma unroll
    for (int b = 0; b < 4; b++) {
        float e = (sh[b] > 0.f) ? sh[b] : expm1f(sh[b]);
        out[(4 * i + b) * 64 + f] = prr[b] - sb * e;
    }
}

extern "C" void kernel_launch(void* const* d_in, const int* in_sizes, int n_in,
                              void* d_out, int out_size) {
    const float* ef    = (const float*)d_in[0];
    const float* L1    = (const float*)d_in[1];
    const float* X     = (const float*)d_in[2];
    const float* W1    = (const float*)d_in[3];
    const float* b1    = (const float*)d_in[4];
    const float* W2    = (const float*)d_in[5];
    const float* b2    = (const float*)d_in[6];
    const float* W3    = (const float*)d_in[7];
    const float* b3    = (const float*)d_in[8];
    const float* Wh    = (const float*)d_in[9];
    const float* Ws1   = (const float*)d_in[10];
    const float* Ws2   = (const float*)d_in[11];
    const float* resW  = (const float*)d_in[12];
    const float* resb  = (const float*)d_in[13];
    const float* alpha = (const float*)d_in[14];
    const float* beta  = (const float*)d_in[15];
    const int*   eidx  = (const int*)d_in[16];
    const int*   jiidx = (const int*)d_in[17];
    float* out = (float*)d_out;

    k_pre<<<512, 256>>>(ef, W1, b1, X, Ws1, Ws2);
    k_pair<<<512, 256>>>(L1, W2, b2, W3, b3, eidx);
    k_mid<<<512, 256>>>(eidx, jiidx, Wh, X, resW, resb, alpha);
    k_out<<<512, 256>>>(eidx, beta, out);
}

// round 11
// speedup vs baseline: 1.6430x; 1.1087x over previous
#include <cuda_runtime.h>
#include <cuda_bf16.h>
#include <math.h>

#define NE 2048
#define NP 32768

// ---------------- static device scratch ----------------
__device__ float g_U[NE * 64];
__device__ float g_V[NE * 64];
__device__ float g_R[NP * 16];
__device__ float4 g_off4[NP * 4];     // per-pair 4 rows of -sgn * R_ji^T R_p
__device__ float g_lvals[NP];
__device__ float g_diag[NE * 16];
__device__ float g_Dinv[NE * 16];
__device__ float4 g_Z4[NE * 64];      // (n, f) -> {z0,z1,z2,z3}
__device__ float4 g_Xt4[NE * 64];     // (n, f) -> X_t rows
__device__ float4 g_P4[NE * 64];      // partial: X@resW+resb - sa*hodge
__device__ float g_Xcol[NE * 64];

// ---------------- K0: U, V, Xcol, Xt ------------------------------------
// grid 512, block 256, 4 nodes/block
__global__ void k_pre(const float* __restrict__ ef, const float* __restrict__ W1,
                      const float* __restrict__ b1, const float* __restrict__ X,
                      const float* __restrict__ Ws1, const float* __restrict__ Ws2) {
    int nl = threadIdx.x >> 6, f = threadIdx.x & 63;
    int n = blockIdx.x * 4 + nl;
    __shared__ float efs[4][64];
    __shared__ float Ysh[4][4][64];
    efs[nl][f] = ef[n * 64 + f];
    float xr[4];
    #pragma unroll
    for (int b = 0; b < 4; b++) xr[b] = X[(4 * n + b) * 64 + f];
    g_Xcol[n * 64 + f] = 0.25f * (xr[0] + xr[1] + xr[2] + xr[3]);
    #pragma unroll
    for (int a = 0; a < 4; a++) {
        float y = 0.f;
        #pragma unroll
        for (int b = 0; b < 4; b++) y = fmaf(Ws1[a * 4 + b], xr[b], y);
        Ysh[nl][a][f] = y;
    }
    __syncthreads();
    float u = b1[f], v = 0.f;
    #pragma unroll 8
    for (int k = 0; k < 64; k++) {
        float x = efs[nl][k];
        u = fmaf(x, W1[k * 64 + f], u);
        v = fmaf(x, W1[(64 + k) * 64 + f], v);
    }
    g_U[n * 64 + f] = u;
    g_V[n * 64 + f] = v;
    float xt[4] = {0.f, 0.f, 0.f, 0.f};
    #pragma unroll 4
    for (int g = 0; g < 64; g++) {
        float w2 = Ws2[g * 64 + f];
        #pragma unroll
        for (int a = 0; a < 4; a++) xt[a] = fmaf(Ysh[nl][a][g], w2, xt[a]);
    }
    float4 o;
    o.x = xt[0]; o.y = xt[1]; o.z = xt[2]; o.w = xt[3];
    g_Xt4[n * 64 + f] = o;
}

// ---------------- K1: per-pair MLP tail -> R, plus L1 gather ------------
// grid 512, block 256: 8 warps x 8 pairs each.
// h1 lives in registers (lane l holds h1[2l], h1[2l+1] per pair); weight rows
// are read ONCE per 8-pair batch as coalesced LDS.32 and h1 values broadcast
// via shuffles -> ~8x fewer smem wavefronts than per-pair weight reads.
__global__ void k_pair(const float* __restrict__ L1,
                       const float* __restrict__ W2, const float* __restrict__ b2,
                       const float* __restrict__ W3, const float* __restrict__ b3,
                       const int* __restrict__ eidx) {
    __shared__ float W2s[64 * 32];   // [k][o] row-major (as given)
    __shared__ float W3s[32 * 16];   // [k][o] row-major (as given)
    __shared__ float b2s[32], b3s[16];
    int tid = threadIdx.x;
    for (int i = tid; i < 64 * 32; i += 256) W2s[i] = W2[i];
    for (int i = tid; i < 32 * 16; i += 256) W3s[i] = W3[i];
    if (tid < 32) b2s[tid] = b2[tid];
    if (tid < 16) b3s[tid] = b3[tid];
    __syncthreads();
    int w = tid >> 5, lane = tid & 31;
    int gw = blockIdx.x * 8 + w;
    int p0 = gw * 8;

    // L1 gather: one pair per lane (lanes 0-7)
    if (lane < 8) {
        int p = p0 + lane;
        int ii = eidx[2 * p], jj = eidx[2 * p + 1];
        g_lvals[p] = L1[(size_t)ii * NE + jj];
    }

    // h1 = relu(U_i + V_j), 2 values per lane per pair
    float hx[8], hy[8];
    #pragma unroll
    for (int pi = 0; pi < 8; pi++) {
        int p = p0 + pi;
        int ii = eidx[2 * p], jj = eidx[2 * p + 1];
        float2 uu = *(const float2*)&g_U[ii * 64 + 2 * lane];
        float2 vv = *(const float2*)&g_V[jj * 64 + 2 * lane];
        hx[pi] = fmaxf(uu.x + vv.x, 0.f);
        hy[pi] = fmaxf(uu.y + vv.y, 0.f);
    }

    // layer 2: 64 -> 32. Each lane owns output o = lane for all 8 pairs.
    float c[8];
    float b2v = b2s[lane];
    #pragma unroll
    for (int pi = 0; pi < 8; pi++) c[pi] = b2v;
    #pragma unroll
    for (int k = 0; k < 64; k++) {
        float wv = W2s[k * 32 + lane];       // coalesced row read, 1 wavefront
        int src = k >> 1;
        #pragma unroll
        for (int pi = 0; pi < 8; pi++) {
            float hval = __shfl_sync(0xffffffffu, (k & 1) ? hy[pi] : hx[pi], src);
            c[pi] = fmaf(hval, wv, c[pi]);
        }
    }
    #pragma unroll
    for (int pi = 0; pi < 8; pi++) c[pi] = fmaxf(c[pi], 0.f);

    // layer 3: 32 -> 16 (no relu). Lanes 0-15 own outputs; all lanes shuffle.
    float r[8];
    float b3v = (lane < 16) ? b3s[lane] : 0.f;
    #pragma unroll
    for (int pi = 0; pi < 8; pi++) r[pi] = b3v;
    #pragma unroll
    for (int k = 0; k < 32; k++) {
        float wv = (lane < 16) ? W3s[k * 16 + lane] : 0.f;
        #pragma unroll
        for (int pi = 0; pi < 8; pi++) {
            float hval = __shfl_sync(0xffffffffu, c[pi], k);
            r[pi] = fmaf(hval, wv, r[pi]);
        }
    }
    if (lane < 16) {
        #pragma unroll
        for (int pi = 0; pi < 8; pi++)
            g_R[(p0 + pi) * 16 + lane] = r[pi];
    }
}

// ---------------- K2: diag/Jacobi/off + Z + hodge + residual partial ----
// grid 512, block 256, 4 nodes (=64 pairs) per block
__global__ void k_mid(const int* __restrict__ eidx, const int* __restrict__ jiidx,
                      const float* __restrict__ Wh, const float* __restrict__ X,
                      const float* __restrict__ resW, const float* __restrict__ resb,
                      const float* __restrict__ alpha) {
    __shared__ float sDb[4][16];
    __shared__ float sDinv[4][16];
    __shared__ float Xcw[20][64];
    __shared__ float Xsh[4][4][64];
    __shared__ float hps[4][64];
    __shared__ int jrel[4][16];
    __shared__ float lv[4][16];
    int tid = threadIdx.x;
    int w = tid >> 5, lane = tid & 31;
    int i0 = blockIdx.x * 4;

    // phase A: diag for nodes i0..i0+3 (warps 0-3)
    if (w < 4) {
        int node = i0 + w;
        float Fm[16];
        #pragma unroll
        for (int x = 0; x < 16; x++) Fm[x] = 0.f;
        if (lane < 16) {
            int p = node * 16 + lane;
            float4 r0 = *(const float4*)&g_R[p * 16];
            float4 r1 = *(const float4*)&g_R[p * 16 + 4];
            float4 r2 = *(const float4*)&g_R[p * 16 + 8];
            float4 r3 = *(const float4*)&g_R[p * 16 + 12];
            float Rv[16] = {r0.x, r0.y, r0.z, r0.w, r1.x, r1.y, r1.z, r1.w,
                            r2.x, r2.y, r2.z, r2.w, r3.x, r3.y, r3.z, r3.w};
            #pragma unroll
            for (int a = 0; a < 4; a++)
                #pragma unroll
                for (int b = 0; b < 4; b++) {
                    float s = 0.f;
                    #pragma unroll
                    for (int c = 0; c < 4; c++) s = fmaf(Rv[c * 4 + a], Rv[c * 4 + b], s);
                    Fm[a * 4 + b] = s;
                }
        }
        #pragma unroll
        for (int x = 0; x < 16; x++) {
            Fm[x] += __shfl_down_sync(0xffffffffu, Fm[x], 8);
            Fm[x] += __shfl_down_sync(0xffffffffu, Fm[x], 4);
            Fm[x] += __shfl_down_sync(0xffffffffu, Fm[x], 2);
            Fm[x] += __shfl_down_sync(0xffffffffu, Fm[x], 1);
        }
        if (lane == 0) {
            #pragma unroll
            for (int x = 0; x < 16; x++) { sDb[w][x] = Fm[x]; g_diag[node * 16 + x] = Fm[x]; }
        }
    }
    __syncthreads();

    // phase B: off blocks (tid<64) + Jacobi (tid 64..67)
    if (tid < 64) {
        int p = i0 * 16 + tid;
        int jp = jiidx[p];
        float l = g_lvals[p];
        float msg = (l > 0.f) ? -1.f : ((l < 0.f) ? 1.f : 0.f);
        float4 a0 = *(const float4*)&g_R[jp * 16];
        float4 a1 = *(const float4*)&g_R[jp * 16 + 4];
        float4 a2 = *(const float4*)&g_R[jp * 16 + 8];
        float4 a3 = *(const float4*)&g_R[jp * 16 + 12];
        float4 b0 = *(const float4*)&g_R[p * 16];
        float4 b1v = *(const float4*)&g_R[p * 16 + 4];
        float4 b2v = *(const float4*)&g_R[p * 16 + 8];
        float4 b3v = *(const float4*)&g_R[p * 16 + 12];
        float Ra[16] = {a0.x, a0.y, a0.z, a0.w, a1.x, a1.y, a1.z, a1.w,
                        a2.x, a2.y, a2.z, a2.w, a3.x, a3.y, a3.z, a3.w};
        float Rb[16] = {b0.x, b0.y, b0.z, b0.w, b1v.x, b1v.y, b1v.z, b1v.w,
                        b2v.x, b2v.y, b2v.z, b2v.w, b3v.x, b3v.y, b3v.z, b3v.w};
        #pragma unroll
        for (int a = 0; a < 4; a++) {
            float4 row;
            float* rp = (float*)&row;
            #pragma unroll
            for (int b = 0; b < 4; b++) {
                float m = 0.f;
                #pragma unroll
                for (int c = 0; c < 4; c++) m = fmaf(Ra[c * 4 + a], Rb[c * 4 + b], m);
                rp[b] = msg * m;
            }
            g_off4[p * 4 + a] = row;
        }
    } else if (tid < 68) {
        int nl = tid - 64;
        const float eps = 1e-4f;
        float A[4][4], V[4][4];
        #pragma unroll
        for (int a = 0; a < 4; a++)
            #pragma unroll
            for (int b = 0; b < 4; b++) {
                A[a][b] = 0.5f * (sDb[nl][a * 4 + b] + sDb[nl][b * 4 + a]);
                V[a][b] = (a == b) ? 1.f : 0.f;
            }
        #pragma unroll
        for (int a = 0; a < 4; a++) A[a][a] += eps;
        const int PI[6] = {0, 0, 0, 1, 1, 2};
        const int QI[6] = {1, 2, 3, 2, 3, 3};
        #pragma unroll
        for (int sweep = 0; sweep < 6; sweep++) {
            #pragma unroll
            for (int r = 0; r < 6; r++) {
                int p = PI[r], q = QI[r];
                float apq = A[p][q];
                if (fabsf(apq) > 1e-20f) {
                    float theta = (A[q][q] - A[p][p]) / (2.f * apq);
                    float t = copysignf(1.f, theta) / (fabsf(theta) + sqrtf(theta * theta + 1.f));
                    float cth = rsqrtf(t * t + 1.f);
                    float sth = t * cth;
                    float app = A[p][p], aqq = A[q][q];
                    A[p][p] = app - t * apq;
                    A[q][q] = aqq + t * apq;
                    A[p][q] = 0.f; A[q][p] = 0.f;
                    #pragma unroll
                    for (int k = 0; k < 4; k++) {
                        if (k != p && k != q) {
                            float akp = A[k][p], akq = A[k][q];
                            A[k][p] = cth * akp - sth * akq; A[p][k] = A[k][p];
                            A[k][q] = sth * akp + cth * akq; A[q][k] = A[k][q];
                        }
                    }
                    #pragma unroll
                    for (int k = 0; k < 4; k++) {
                        float vkp = V[k][p], vkq = V[k][q];
                        V[k][p] = cth * vkp - sth * vkq;
                        V[k][q] = sth * vkp + cth * vkq;
                    }
                }
            }
        }
        float invs[4];
        #pragma unroll
        for (int k = 0; k < 4; k++) invs[k] = rsqrtf(fmaxf(A[k][k], eps));
        int gnode = i0 + nl;
        #pragma unroll
        for (int a = 0; a < 4; a++)
            #pragma unroll
            for (int b = 0; b < 4; b++) {
                float s = 0.f;
                #pragma unroll
                for (int k = 0; k < 4; k++) s = fmaf(V[a][k] * invs[k], V[b][k], s);
                sDinv[nl][a * 4 + b] = s;
                g_Dinv[gnode * 16 + a * 4 + b] = s;
            }
    }

    // phase D staging (independent of B results): Xcol window, X rows, meta
    #pragma unroll
    for (int t = 0; t < 5; t++) {
        int idx = tid + t * 256;
        int row = idx >> 6, ff = idx & 63;
        int src = (i0 - 8 + row) & (NE - 1);
        Xcw[row][ff] = g_Xcol[src * 64 + ff];
    }
    #pragma unroll
    for (int t = 0; t < 4; t++) {
        int idx = tid + t * 256;
        int nn = idx >> 8, rest = idx & 255;
        int b = rest >> 6, ff = rest & 63;
        Xsh[nn][b][ff] = X[(4 * (i0 + nn) + b) * 64 + ff];
    }
    if (tid < 64) {
        int nn = tid >> 4, k = tid & 15;
        int pp = (i0 + nn) * 16 + k;
        int j = eidx[2 * pp + 1];
        jrel[nn][k] = (j - i0 + 8) & (NE - 1);
        lv[nn][k] = fabsf(g_lvals[pp]);
    }
    __syncthreads();

    int nl = tid >> 6, f = tid & 63;
    int n = i0 + nl;

    // phase C: Z = Dinv @ Xt
    {
        float4 xt = g_Xt4[n * 64 + f];
        float dv[16];
        #pragma unroll
        for (int x = 0; x < 16; x++) dv[x] = sDinv[nl][x];
        float4 z;
        z.x = fmaf(dv[0], xt.x, fmaf(dv[1], xt.y, fmaf(dv[2], xt.z, dv[3] * xt.w)));
        z.y = fmaf(dv[4], xt.x, fmaf(dv[5], xt.y, fmaf(dv[6], xt.z, dv[7] * xt.w)));
        z.z = fmaf(dv[8], xt.x, fmaf(dv[9], xt.y, fmaf(dv[10], xt.z, dv[11] * xt.w)));
        z.w = fmaf(dv[12], xt.x, fmaf(dv[13], xt.y, fmaf(dv[14], xt.z, dv[15] * xt.w)));
        g_Z4[n * 64 + f] = z;
    }

    // phase D: hodge + residual partial
    float s = 0.f;
    #pragma unroll
    for (int p = 0; p < 16; p++) s += lv[nl][p];
    float inv = 1.f / (s + 1e-8f);
    float hp = Xcw[8 + nl][f];
    #pragma unroll
    for (int p = 0; p < 16; p++)
        hp = fmaf(lv[nl][p] * inv, Xcw[jrel[nl][p]][f], hp);
    hps[nl][f] = hp;
    __syncthreads();
    float h = 0.f;
    #pragma unroll 4
    for (int g = 0; g < 64; g++) h = fmaf(hps[nl][g], Wh[g * 64 + f], h);
    float sa = 1.f / (1.f + expf(-alpha[0]));
    float bb = resb[f];
    float r[4];
    #pragma unroll
    for (int b = 0; b < 4; b++) r[b] = bb;
    #pragma unroll 4
    for (int k = 0; k < 64; k++) {
        float wv = resW[k * 64 + f];
        #pragma unroll
        for (int b = 0; b < 4; b++) r[b] = fmaf(Xsh[nl][b][k], wv, r[b]);
    }
    float4 pr;
    pr.x = r[0] - sa * h; pr.y = r[1] - sa * h;
    pr.z = r[2] - sa * h; pr.w = r[3] - sa * h;
    g_P4[n * 64 + f] = pr;
}

// ---------------- K3: sheaf + combine -----------------------------------
// grid 512, block 256, 4 nodes/block (R7 sheaf structure)
__global__ void k_out(const int* __restrict__ eidx, const float* __restrict__ beta,
                      float* __restrict__ out) {
    int tid = threadIdx.x;
    int nl = tid >> 6, f = tid & 63;
    int i0 = blockIdx.x * 4;
    int i = i0 + nl;
    __shared__ float4 Z4sh[20][64];
    __shared__ float4 offs4[4][64];
    __shared__ int jrel[4][16];

    #pragma unroll
    for (int t = 0; t < 5; t++) {
        int idx = tid + t * 256;
        int row = idx >> 6, ff = idx & 63;
        int src = (i0 - 8 + row) & (NE - 1);
        Z4sh[row][ff] = g_Z4[src * 64 + ff];
    }
    offs4[nl][f] = g_off4[i * 64 + f];
    if (f < 16) {
        int pp = 16 * i + f;
        int j = eidx[2 * pp + 1];
        jrel[nl][f] = (j - i0 + 8) & (NE - 1);
    }
    __syncthreads();

    float4 zi = Z4sh[8 + nl][f];
    const float4* dgr = (const float4*)&g_diag[i * 16];
    float accs[4];
    #pragma unroll
    for (int a = 0; a < 4; a++) {
        float4 d = dgr[a];
        accs[a] = fmaf(d.x, zi.x, fmaf(d.y, zi.y, fmaf(d.z, zi.z, d.w * zi.w)));
    }
    #pragma unroll
    for (int k = 0; k < 16; k++) {
        float4 zj = Z4sh[jrel[nl][k]][f];
        #pragma unroll
        for (int a = 0; a < 4; a++) {
            float4 o = offs4[nl][k * 4 + a];
            accs[a] = fmaf(o.x, zj.x, fmaf(o.y, zj.y, fmaf(o.z, zj.z, fmaf(o.w, zj.w, accs[a]))));
        }
    }
    const float4* dvr = (const float4*)&g_Dinv[i * 16];
    float sh[4];
    #pragma unroll
    for (int a = 0; a < 4; a++) {
        float4 d = dvr[a];
        sh[a] = fmaf(d.x, accs[0], fmaf(d.y, accs[1], fmaf(d.z, accs[2], d.w * accs[3])));
    }

    float4 pr = g_P4[i * 64 + f];
    float sb = 1.f / (1.f + expf(-beta[0]));
    float prr[4] = {pr.x, pr.y, pr.z, pr.w};
    #pragma unroll
    for (int b = 0; b < 4; b++) {
        float e = (sh[b] > 0.f) ? sh[b] : expm1f(sh[b]);
        out[(4 * i + b) * 64 + f] = prr[b] - sb * e;
    }
}

extern "C" void kernel_launch(void* const* d_in, const int* in_sizes, int n_in,
                              void* d_out, int out_size) {
    const float* ef    = (const float*)d_in[0];
    const float* L1    = (const float*)d_in[1];
    const float* X     = (const float*)d_in[2];
    const float* W1    = (const float*)d_in[3];
    const float* b1    = (const float*)d_in[4];
    const float* W2    = (const float*)d_in[5];
    const float* b2    = (const float*)d_in[6];
    const float* W3    = (const float*)d_in[7];
    const float* b3    = (const float*)d_in[8];
    const float* Wh    = (const float*)d_in[9];
    const float* Ws1   = (const float*)d_in[10];
    const float* Ws2   = (const float*)d_in[11];
    const float* resW  = (const float*)d_in[12];
    const float* resb  = (const float*)d_in[13];
    const float* alpha = (const float*)d_in[14];
    const float* beta  = (const float*)d_in[15];
    const int*   eidx  = (const int*)d_in[16];
    const int*   jiidx = (const int*)d_in[17];
    float* out = (float*)d_out;

    k_pre<<<512, 256>>>(ef, W1, b1, X, Ws1, Ws2);
    k_pair<<<512, 256>>>(L1, W2, b2, W3, b3, eidx);
    k_mid<<<512, 256>>>(eidx, jiidx, Wh, X, resW, resb, alpha);
    k_out<<<512, 256>>>(eidx, beta, out);
}